// round 6
// baseline (speedup 1.0000x reference)
#include <cuda_runtime.h>
#include <math.h>

#define NB   32
#define NS   4096
#define ND   64
#define NL   13
#define NWR  13
#define NCLS 2
#define ROWS (NB*NS)          // 131072
#define SD   (NS*ND)          // 262144
#define VOCAB 512

__device__ float g_Vtab[VOCAB*ND];                  // [v][64]
__device__ float g_Ftab[(size_t)NWR*VOCAB*16];      // [k][v][16] (13 used)
__device__ float g_Zdump[(size_t)ROWS*ND];          // fallback Z sink

__device__ __forceinline__ float gelu_exact(float x) {
    return 0.5f * x * (1.0f + erff(x * 0.7071067811865476f));
}

// ---------------------------------------------------------------------------
// Tables: grid (16, 14), block 512. y==0 -> Vtab, y==1..13 -> Ftab[y-1].
// ---------------------------------------------------------------------------
__global__ __launch_bounds__(512) void tables_kernel(
    const float* __restrict__ emb,
    const float* __restrict__ fW1, const float* __restrict__ fb1,
    const float* __restrict__ fW2, const float* __restrict__ fb2,
    const float* __restrict__ vW1, const float* __restrict__ vb1,
    const float* __restrict__ vW2, const float* __restrict__ vb2) {
    extern __shared__ float sm[];
    float* Es  = sm;                    // 2048
    float* W1s = sm + 2048;             // 8192
    float* Hs  = sm + 10240;            // 128*33 = 4224
    float* W2s = sm + 14464;            // up to 8192

    const int y  = blockIdx.y;
    const int v0 = blockIdx.x * 32;
    const int t  = threadIdx.x;

    for (int i = t; i < 2048; i += 512) Es[i] = emb[v0*64 + i];
    const float* W1g = (y == 0) ? vW1 : fW1 + (size_t)(y-1)*64*128;
    for (int i = t; i < 8192; i += 512) W1s[i] = W1g[i];
    if (y == 0) {
        for (int i = t; i < 8192; i += 512) W2s[i] = vW2[i];
    } else {
        const float* W2g = fW2 + (size_t)(y-1)*128*NL;
        for (int i = t; i < 128*NL; i += 512) W2s[i] = W2g[i];
    }
    __syncthreads();

    {
        const int h  = t & 127;
        const int rg = t >> 7;          // 0..3 -> 8 rows each
        float w[64];
#pragma unroll
        for (int d = 0; d < 64; d++) w[d] = W1s[d*128 + h];
        const float b1 = (y == 0) ? vb1[h] : fb1[(y-1)*128 + h];
#pragma unroll 1
        for (int rr = 0; rr < 8; rr++) {
            int r = rg*8 + rr;
            float acc = b1;
#pragma unroll
            for (int d = 0; d < 64; d++) acc = fmaf(Es[r*64 + d], w[d], acc);
            Hs[h*33 + r] = gelu_exact(acc);
        }
    }
    __syncthreads();

    if (y == 0) {
        const int d = t & 63, rgrp = t >> 6;
#pragma unroll 1
        for (int rr = 0; rr < 4; rr++) {
            int r = rgrp*4 + rr;
            float acc = vb2[d];
#pragma unroll 8
            for (int h2 = 0; h2 < 128; h2++)
                acc = fmaf(Hs[h2*33 + r], W2s[h2*64 + d], acc);
            g_Vtab[(size_t)(v0 + r)*64 + d] = acc;
        }
    } else {
        const int k = y - 1;
        if (t < 32*NL) {
            int l = t >> 5, r = t & 31;
            float acc = fb2[k*NL + l];
#pragma unroll 8
            for (int h2 = 0; h2 < 128; h2++)
                acc = fmaf(Hs[h2*33 + r], W2s[h2*NL + l], acc);
            g_Ftab[((size_t)k*VOCAB + v0 + r)*16 + l] = acc;
        }
    }
}

// ---------------------------------------------------------------------------
// Logits
// ---------------------------------------------------------------------------
__global__ __launch_bounds__(256) void logits_kernel(
    const int* __restrict__ tok,
    const float* __restrict__ finW, const float* __restrict__ finb,
    float* __restrict__ out) {
    const int s = blockIdx.x & 7;
    const int c = (blockIdx.x >> 3) & 1;
    const int b = blockIdx.x >> 4;
    const int t = threadIdx.x;
    const int chunk = SD/4/8;   // 8192 float4

    const float4* Vt4 = (const float4*)g_Vtab;
    const float4* w   = (const float4*)(finW + (size_t)c*SD) + s*chunk;
    const int*    tkb = tok + (size_t)b*NS;

    float acc = 0.f;
    for (int i = t; i < chunk; i += 256) {
        int gi   = s*chunk + i;
        int srow = gi >> 4;
        int d4   = gi & 15;
        float4 vv = Vt4[tkb[srow]*16 + d4];
        float4 ww = w[i];
        acc = fmaf(vv.x, ww.x, acc);
        acc = fmaf(vv.y, ww.y, acc);
        acc = fmaf(vv.z, ww.z, acc);
        acc = fmaf(vv.w, ww.w, acc);
    }
    __shared__ float red[256];
    red[t] = acc;
    __syncthreads();
#pragma unroll
    for (int sft = 128; sft > 0; sft >>= 1) {
        if (t < sft) red[t] += red[t + sft];
        __syncthreads();
    }
    if (t == 0) atomicAdd(&out[b*NCLS + c], red[0] + (s == 0 ? finb[c] : 0.f));
}

// ---------------------------------------------------------------------------
// Fused chord, all 13 rounds. Block = (b, cp 0..15) -> 4 columns c0=cp*4.
// 512 threads; thread t owns i = t + 512m (m=0..7).
// Links 0/512/1024/2048 from registers; links 1..256 from one float4 smem
// plane; F read from L2-hot Ftab with one-step register prefetch.
// smem 74KB -> 3 CTAs/SM.
// ---------------------------------------------------------------------------
__global__ __launch_bounds__(512, 3) void chord_all_kernel(
    const int* __restrict__ tok, float* __restrict__ outZ) {
    extern __shared__ float sm[];
    float4* Zs = (float4*)sm;            // [i], cols c0..c0+3   (64 KB)
    float*  Vs = sm + NS*4;              // [v*5 + c]            (10 KB)

    const int b  = blockIdx.x >> 4;
    const int cp = blockIdx.x & 15;
    const int c0 = cp * 4;
    const int t  = threadIdx.x;

    // own-row tokens
    int v[8];
    {
        const int* tkb = tok + (size_t)b*NS;
#pragma unroll
        for (int m = 0; m < 8; m++) v[m] = tkb[t + 512*m];
    }
    // stage Vs: Vs[v*5 + c] = Vtab[v][c0+c]
    {
        float4 a = *(const float4*)(g_Vtab + (size_t)t*64 + c0);
        float* dst = Vs + t*5;
        dst[0]=a.x; dst[1]=a.y; dst[2]=a.z; dst[3]=a.w;
    }
    __syncthreads();

    // Z := V
    float4 zreg[8];
#pragma unroll
    for (int m = 0; m < 8; m++) {
        const float* vv = Vs + v[m]*5;
        zreg[m] = make_float4(vv[0], vv[1], vv[2], vv[3]);
        Zs[t + 512*m] = zreg[m];
    }
    __syncthreads();

    // prefetch F row for k=0, m=0
    const float4* Ft4 = (const float4*)g_Ftab;
    float4 fn0, fn1, fn2, fn3;
    {
        const float4* fr = Ft4 + (size_t)v[0]*4;
        fn0 = fr[0]; fn1 = fr[1]; fn2 = fr[2]; fn3 = fr[3];
    }

    float4 acc[8];
#pragma unroll 1
    for (int k = 0; k < NWR; k++) {
#pragma unroll
        for (int m = 0; m < 8; m++) {
            const int i = t + 512*m;
            // current F regs
            float4 f0v = fn0, f1v = fn1, f2v = fn2;
            // prefetch next
            {
                int kn = (m == 7) ? k + 1 : k;
                int vn = v[(m + 1) & 7];
                if (kn < NWR) {
                    const float4* fr = Ft4 + ((size_t)kn*VOCAB + vn)*4;
                    fn0 = fr[0]; fn1 = fr[1]; fn2 = fr[2]; fn3 = fr[3];
                }
            }
            const float f0  = f0v.x, f1  = f0v.y, f2  = f0v.z, f3  = f0v.w;
            const float f4  = f1v.x, f5  = f1v.y, f6  = f1v.z, f7  = f1v.w;
            const float f8  = f2v.x, f9  = f2v.y, f10 = f2v.z, f11 = f2v.w;
            const float f12 = fn3.x;  // careful: fn3 was overwritten—use saved
            (void)f12;

            // V residual
            const float* vv = Vs + v[m]*5;
            float4 a = make_float4(vv[0], vv[1], vv[2], vv[3]);

            // register links: off 0, 512, 1024, 2048 -> f0, f10, f11, f12
            const int m1 = (m+1)&7, m2 = (m+2)&7, m4 = (m+4)&7;
            const float fA = f0, fB = f10, fC = f11, fD = f2v.w; // placeholder
            (void)fA;(void)fB;(void)fC;(void)fD;

            // NOTE: f12 must come from the *current* row's 4th quad, which we
            // saved before overwriting fn3:
            // handled below via fcur3 (see fix)
            float fcur12;
            {
                // recompute from f2v? f12 is element 12 = quad3.x of current row.
                // We kept current quad3 in f3v_saved:
                fcur12 = 0.f; // replaced below
            }
            (void)fcur12;

            // --- actual link math (f12 passed via f3v_cur) ---
            float4 f3v_cur = make_float4(0.f,0.f,0.f,0.f);
            (void)f3v_cur;

            a.x = fmaf(f0, zreg[m].x, a.x); a.y = fmaf(f0, zreg[m].y, a.y);
            a.z = fmaf(f0, zreg[m].z, a.z); a.w = fmaf(f0, zreg[m].w, a.w);
            a.x = fmaf(f10, zreg[m1].x, a.x); a.y = fmaf(f10, zreg[m1].y, a.y);
            a.z = fmaf(f10, zreg[m1].z, a.z); a.w = fmaf(f10, zreg[m1].w, a.w);
            a.x = fmaf(f11, zreg[m2].x, a.x); a.y = fmaf(f11, zreg[m2].y, a.y);
            a.z = fmaf(f11, zreg[m2].z, a.z); a.w = fmaf(f11, zreg[m2].w, a.w);

            // smem links off 1..256 (f1..f9)
            const float fs[9] = {f1,f2,f3,f4,f5,f6,f7,f8,f9};
            const int offs[9] = {1,2,4,8,16,32,64,128,256};
#pragma unroll
            for (int li = 0; li < 9; li++) {
                const int j = (i + offs[li]) & (NS-1);
                const float fl = fs[li];
                float4 z = Zs[j];
                a.x = fmaf(fl, z.x, a.x); a.y = fmaf(fl, z.y, a.y);
                a.z = fmaf(fl, z.z, a.z); a.w = fmaf(fl, z.w, a.w);
            }
            acc[m] = a;
        }
        // f12 (off 2048 -> zreg[m4]) was elided above; apply it here using a
        // second pass over the saved quad values is impossible — so instead
        // f12 is folded in the loop below BEFORE writeback using re-read F.
        {
            const float* Fk = g_Ftab + (size_t)k*VOCAB*16;
#pragma unroll
            for (int m = 0; m < 8; m++) {
                const float f12 = Fk[v[m]*16 + 12];
                const int m4 = (m+4)&7;
                acc[m].x = fmaf(f12, zreg[m4].x, acc[m].x);
                acc[m].y = fmaf(f12, zreg[m4].y, acc[m].y);
                acc[m].z = fmaf(f12, zreg[m4].z, acc[m].z);
                acc[m].w = fmaf(f12, zreg[m4].w, acc[m].w);
            }
        }
        __syncthreads();
#pragma unroll
        for (int m = 0; m < 8; m++) {
            zreg[m] = acc[m];
            Zs[t + 512*m] = acc[m];
        }
        __syncthreads();
    }

    // final Z -> gmem
#pragma unroll
    for (int m = 0; m < 8; m++) {
        const int i = t + 512*m;
        *(float4*)(outZ + ((size_t)b*NS + i)*64 + c0) = acc[m];
    }
}

// ---------------------------------------------------------------------------
extern "C" void kernel_launch(void* const* d_in, const int* in_sizes, int n_in,
                              void* d_out, int out_size) {
    const int*   tok  = (const int*)  d_in[0];
    const float* emb  = (const float*)d_in[1];
    const float* fW1  = (const float*)d_in[2];
    const float* fb1  = (const float*)d_in[3];
    const float* fW2  = (const float*)d_in[4];
    const float* fb2  = (const float*)d_in[5];
    const float* vW1  = (const float*)d_in[6];
    const float* vb1  = (const float*)d_in[7];
    const float* vW2  = (const float*)d_in[8];
    const float* vb2  = (const float*)d_in[9];
    const float* finW = (const float*)d_in[10];
    const float* finb = (const float*)d_in[11];
    float* out = (float*)d_out;

    const int tables_smem = (2048 + 8192 + 4224 + 8192) * 4;   // 90624
    const int chord_smem  = (NS*4 + VOCAB*5) * 4;              // 75776
    cudaFuncSetAttribute(tables_kernel,    cudaFuncAttributeMaxDynamicSharedMemorySize, tables_smem);
    cudaFuncSetAttribute(chord_all_kernel, cudaFuncAttributeMaxDynamicSharedMemorySize, chord_smem);

    dim3 tgrid(16, 14);
    tables_kernel<<<tgrid, 512, tables_smem>>>(emb, fW1, fb1, fW2, fb2,
                                               vW1, vb1, vW2, vb2);

    cudaMemsetAsync(out, 0, NB*NCLS*sizeof(float));
    logits_kernel<<<NB*NCLS*8, 256>>>(tok, finW, finb, out);

    float* zdst;
    if (out_size >= NB*NCLS + ROWS*ND) zdst = out + NB*NCLS;
    else cudaGetSymbolAddress((void**)&zdst, g_Zdump);
    chord_all_kernel<<<NB*16, 512, chord_smem>>>(tok, zdst);
}

// round 7
// speedup vs baseline: 2.6160x; 2.6160x over previous
#include <cuda_runtime.h>
#include <math.h>

#define NB   32
#define NS   4096
#define ND   64
#define NL   13
#define NWR  13
#define NCLS 2
#define ROWS (NB*NS)          // 131072
#define SD   (NS*ND)          // 262144
#define VOCAB 512

__device__ float g_Vtab[VOCAB*ND];                  // [v][64]
__device__ float g_Ftab[(size_t)NWR*VOCAB*16];      // [k][v][16] (13 used)
__device__ float g_FgT[(size_t)NWR*NB*NS*16];       // [k][b][i][16]  109 MB
__device__ float g_Zdump[(size_t)ROWS*ND];          // fallback Z sink

__device__ __forceinline__ float gelu_exact(float x) {
    return 0.5f * x * (1.0f + erff(x * 0.7071067811865476f));
}

// ---------------------------------------------------------------------------
// Tables: grid (16, 14), block 512. y==0 -> Vtab, y==1..13 -> Ftab[y-1].
// ---------------------------------------------------------------------------
__global__ __launch_bounds__(512) void tables_kernel(
    const float* __restrict__ emb,
    const float* __restrict__ fW1, const float* __restrict__ fb1,
    const float* __restrict__ fW2, const float* __restrict__ fb2,
    const float* __restrict__ vW1, const float* __restrict__ vb1,
    const float* __restrict__ vW2, const float* __restrict__ vb2) {
    extern __shared__ float sm[];
    float* Es  = sm;                    // 2048
    float* W1s = sm + 2048;             // 8192
    float* Hs  = sm + 10240;            // 128*33 = 4224
    float* W2s = sm + 14464;            // up to 8192

    const int y  = blockIdx.y;
    const int v0 = blockIdx.x * 32;
    const int t  = threadIdx.x;

    for (int i = t; i < 2048; i += 512) Es[i] = emb[v0*64 + i];
    const float* W1g = (y == 0) ? vW1 : fW1 + (size_t)(y-1)*64*128;
    for (int i = t; i < 8192; i += 512) W1s[i] = W1g[i];
    if (y == 0) {
        for (int i = t; i < 8192; i += 512) W2s[i] = vW2[i];
    } else {
        const float* W2g = fW2 + (size_t)(y-1)*128*NL;
        for (int i = t; i < 128*NL; i += 512) W2s[i] = W2g[i];
    }
    __syncthreads();

    // stage 1 with 4 independent accumulators
    {
        const int h  = t & 127;
        const int rg = t >> 7;          // 0..3 -> 8 rows each
        float w[64];
#pragma unroll
        for (int d = 0; d < 64; d++) w[d] = W1s[d*128 + h];
        const float b1 = (y == 0) ? vb1[h] : fb1[(y-1)*128 + h];
#pragma unroll 1
        for (int rr = 0; rr < 8; rr++) {
            int r = rg*8 + rr;
            float a0=0.f, a1=0.f, a2=0.f, a3=0.f;
#pragma unroll
            for (int d4 = 0; d4 < 16; d4++) {
                a0 = fmaf(Es[r*64 + 4*d4+0], w[4*d4+0], a0);
                a1 = fmaf(Es[r*64 + 4*d4+1], w[4*d4+1], a1);
                a2 = fmaf(Es[r*64 + 4*d4+2], w[4*d4+2], a2);
                a3 = fmaf(Es[r*64 + 4*d4+3], w[4*d4+3], a3);
            }
            Hs[h*33 + r] = gelu_exact(b1 + ((a0+a1)+(a2+a3)));
        }
    }
    __syncthreads();

    if (y == 0) {
        const int d = t & 63, rgrp = t >> 6;
#pragma unroll 1
        for (int rr = 0; rr < 4; rr++) {
            int r = rgrp*4 + rr;
            float a0=0.f, a1=0.f, a2=0.f, a3=0.f;
#pragma unroll
            for (int h4 = 0; h4 < 32; h4++) {
                a0 = fmaf(Hs[(4*h4+0)*33 + r], W2s[(4*h4+0)*64 + d], a0);
                a1 = fmaf(Hs[(4*h4+1)*33 + r], W2s[(4*h4+1)*64 + d], a1);
                a2 = fmaf(Hs[(4*h4+2)*33 + r], W2s[(4*h4+2)*64 + d], a2);
                a3 = fmaf(Hs[(4*h4+3)*33 + r], W2s[(4*h4+3)*64 + d], a3);
            }
            g_Vtab[(size_t)(v0 + r)*64 + d] = vb2[d] + ((a0+a1)+(a2+a3));
        }
    } else {
        const int k = y - 1;
        if (t < 32*NL) {
            int l = t >> 5, r = t & 31;
            float a0=0.f, a1=0.f, a2=0.f, a3=0.f;
#pragma unroll
            for (int h4 = 0; h4 < 32; h4++) {
                a0 = fmaf(Hs[(4*h4+0)*33 + r], W2s[(4*h4+0)*NL + l], a0);
                a1 = fmaf(Hs[(4*h4+1)*33 + r], W2s[(4*h4+1)*NL + l], a1);
                a2 = fmaf(Hs[(4*h4+2)*33 + r], W2s[(4*h4+2)*NL + l], a2);
                a3 = fmaf(Hs[(4*h4+3)*33 + r], W2s[(4*h4+3)*NL + l], a3);
            }
            g_Ftab[((size_t)k*VOCAB + v0 + r)*16 + l] = fb2[k*NL + l] + ((a0+a1)+(a2+a3));
        }
    }
}

// ---------------------------------------------------------------------------
// F expansion: FgT[k][b][i][0..15] = Ftab[k][tok[b][i]][0..15]
// Thread per (kb, i): 64B contiguous write per lane (fully-used lines).
// ---------------------------------------------------------------------------
__global__ __launch_bounds__(256) void fgather_kernel(const int* __restrict__ tok) {
    const int i  = blockIdx.x * 256 + threadIdx.x;
    const int kb = blockIdx.y;          // k*NB + b
    const int k  = kb >> 5;
    const int b  = kb & 31;
    const int v  = tok[(size_t)b*NS + i];

    const float4* src = (const float4*)g_Ftab + ((size_t)k*VOCAB + v)*4;
    float4* dst = (float4*)g_FgT + ((size_t)kb*NS + i)*4;
    float4 q0 = src[0], q1 = src[1], q2 = src[2], q3 = src[3];
    dst[0] = q0; dst[1] = q1; dst[2] = q2; dst[3] = q3;
}

// ---------------------------------------------------------------------------
// Logits
// ---------------------------------------------------------------------------
__global__ __launch_bounds__(256) void logits_kernel(
    const int* __restrict__ tok,
    const float* __restrict__ finW, const float* __restrict__ finb,
    float* __restrict__ out) {
    const int s = blockIdx.x & 7;
    const int c = (blockIdx.x >> 3) & 1;
    const int b = blockIdx.x >> 4;
    const int t = threadIdx.x;
    const int chunk = SD/4/8;   // 8192 float4

    const float4* Vt4 = (const float4*)g_Vtab;
    const float4* w   = (const float4*)(finW + (size_t)c*SD) + s*chunk;
    const int*    tkb = tok + (size_t)b*NS;

    float acc = 0.f;
    for (int i = t; i < chunk; i += 256) {
        int gi   = s*chunk + i;
        int srow = gi >> 4;
        int d4   = gi & 15;
        float4 vv = Vt4[tkb[srow]*16 + d4];
        float4 ww = w[i];
        acc = fmaf(vv.x, ww.x, acc);
        acc = fmaf(vv.y, ww.y, acc);
        acc = fmaf(vv.z, ww.z, acc);
        acc = fmaf(vv.w, ww.w, acc);
    }
    __shared__ float red[256];
    red[t] = acc;
    __syncthreads();
#pragma unroll
    for (int sft = 128; sft > 0; sft >>= 1) {
        if (t < sft) red[t] += red[t + sft];
        __syncthreads();
    }
    if (t == 0) atomicAdd(&out[b*NCLS + c], red[0] + (s == 0 ? finb[c] : 0.f));
}

// ---------------------------------------------------------------------------
// Fused chord, all 13 rounds. Block = (b, cp 0..15) -> 4 cols c0=cp*4.
// Thread t owns i = t + 512m (m=0..7). Links 0/512/1024/2048 from registers
// (zreg); links 1..256 from the float4 smem plane. F coefficients come from
// pre-expanded g_FgT[k][b][i][16], software-pipelined one m ahead.
// ---------------------------------------------------------------------------
__global__ __launch_bounds__(512, 1) void chord_all_kernel(
    const int* __restrict__ tok, float* __restrict__ outZ) {
    extern __shared__ float sm[];
    float4* Zs = (float4*)sm;            // [i], cols c0..c0+3 (64 KB)
    float*  Vs = sm + NS*4;              // [v*5 + c] (10 KB)

    const int b  = blockIdx.x >> 4;
    const int cp = blockIdx.x & 15;
    const int c0 = cp * 4;
    const int t  = threadIdx.x;

    int v[8];
    {
        const int* tkb = tok + (size_t)b*NS;
#pragma unroll
        for (int m = 0; m < 8; m++) v[m] = tkb[t + 512*m];
    }
    {
        float4 a = *(const float4*)(g_Vtab + (size_t)t*64 + c0);
        float* dst = Vs + t*5;
        dst[0]=a.x; dst[1]=a.y; dst[2]=a.z; dst[3]=a.w;
    }
    __syncthreads();

    // Z := V
    float4 zreg[8];
#pragma unroll
    for (int m = 0; m < 8; m++) {
        const float* vv = Vs + v[m]*5;
        zreg[m] = make_float4(vv[0], vv[1], vv[2], vv[3]);
        Zs[t + 512*m] = zreg[m];
    }
    __syncthreads();

    const float4* Fg4 = (const float4*)g_FgT;
    // prefetch F row (k=0, m=0)
    float4 p0, p1, p2, p3;
    {
        const float4* fr = Fg4 + ((size_t)(0*NB + b)*NS + t)*4;
        p0 = fr[0]; p1 = fr[1]; p2 = fr[2]; p3 = fr[3];
    }

    float4 acc[8];
#pragma unroll 1
    for (int k = 0; k < NWR; k++) {
#pragma unroll
        for (int m = 0; m < 8; m++) {
            const int i = t + 512*m;
            // take current F row
            const float4 q0 = p0, q1 = p1, q2 = p2, q3 = p3;
            // prefetch next (m+1, or next k's m=0; clamp at end)
            {
                const int kn = (m == 7) ? ((k + 1 < NWR) ? k + 1 : k) : k;
                const int in = (m == 7) ? t : i + 512;
                const float4* fr = Fg4 + ((size_t)(kn*NB + b)*NS + in)*4;
                p0 = fr[0]; p1 = fr[1]; p2 = fr[2]; p3 = fr[3];
            }
            const float f0  = q0.x, f1  = q0.y, f2  = q0.z, f3  = q0.w;
            const float f4  = q1.x, f5  = q1.y, f6  = q1.z, f7  = q1.w;
            const float f8  = q2.x, f9  = q2.y, f10 = q2.z, f11 = q2.w;
            const float f12 = q3.x;

            // V residual
            const float* vv = Vs + v[m]*5;
            float4 a = make_float4(vv[0], vv[1], vv[2], vv[3]);

            // register links: off 0 (f0), 512 (f10), 1024 (f11), 2048 (f12)
            const int m1 = (m+1)&7, m2 = (m+2)&7, m4 = (m+4)&7;
            a.x = fmaf(f0,  zreg[m ].x, a.x); a.y = fmaf(f0,  zreg[m ].y, a.y);
            a.z = fmaf(f0,  zreg[m ].z, a.z); a.w = fmaf(f0,  zreg[m ].w, a.w);
            a.x = fmaf(f10, zreg[m1].x, a.x); a.y = fmaf(f10, zreg[m1].y, a.y);
            a.z = fmaf(f10, zreg[m1].z, a.z); a.w = fmaf(f10, zreg[m1].w, a.w);
            a.x = fmaf(f11, zreg[m2].x, a.x); a.y = fmaf(f11, zreg[m2].y, a.y);
            a.z = fmaf(f11, zreg[m2].z, a.z); a.w = fmaf(f11, zreg[m2].w, a.w);
            a.x = fmaf(f12, zreg[m4].x, a.x); a.y = fmaf(f12, zreg[m4].y, a.y);
            a.z = fmaf(f12, zreg[m4].z, a.z); a.w = fmaf(f12, zreg[m4].w, a.w);

            // smem links: off 1..256 (f1..f9)
            const float fs[9] = {f1,f2,f3,f4,f5,f6,f7,f8,f9};
            const int offs[9] = {1,2,4,8,16,32,64,128,256};
#pragma unroll
            for (int li = 0; li < 9; li++) {
                const int j = (i + offs[li]) & (NS-1);
                const float fl = fs[li];
                float4 z = Zs[j];
                a.x = fmaf(fl, z.x, a.x); a.y = fmaf(fl, z.y, a.y);
                a.z = fmaf(fl, z.z, a.z); a.w = fmaf(fl, z.w, a.w);
            }
            acc[m] = a;
        }
        __syncthreads();
#pragma unroll
        for (int m = 0; m < 8; m++) {
            zreg[m] = acc[m];
            Zs[t + 512*m] = acc[m];
        }
        __syncthreads();
    }

    // final Z -> gmem
#pragma unroll
    for (int m = 0; m < 8; m++) {
        const int i = t + 512*m;
        *(float4*)(outZ + ((size_t)b*NS + i)*64 + c0) = acc[m];
    }
}

// ---------------------------------------------------------------------------
extern "C" void kernel_launch(void* const* d_in, const int* in_sizes, int n_in,
                              void* d_out, int out_size) {
    const int*   tok  = (const int*)  d_in[0];
    const float* emb  = (const float*)d_in[1];
    const float* fW1  = (const float*)d_in[2];
    const float* fb1  = (const float*)d_in[3];
    const float* fW2  = (const float*)d_in[4];
    const float* fb2  = (const float*)d_in[5];
    const float* vW1  = (const float*)d_in[6];
    const float* vb1  = (const float*)d_in[7];
    const float* vW2  = (const float*)d_in[8];
    const float* vb2  = (const float*)d_in[9];
    const float* finW = (const float*)d_in[10];
    const float* finb = (const float*)d_in[11];
    float* out = (float*)d_out;

    const int tables_smem = (2048 + 8192 + 4224 + 8192) * 4;   // 90624
    const int chord_smem  = (NS*4 + VOCAB*5) * 4;              // 75776
    cudaFuncSetAttribute(tables_kernel,    cudaFuncAttributeMaxDynamicSharedMemorySize, tables_smem);
    cudaFuncSetAttribute(chord_all_kernel, cudaFuncAttributeMaxDynamicSharedMemorySize, chord_smem);

    dim3 tgrid(16, 14);
    tables_kernel<<<tgrid, 512, tables_smem>>>(emb, fW1, fb1, fW2, fb2,
                                               vW1, vb1, vW2, vb2);

    dim3 fggrid(NS/256, NWR*NB);
    fgather_kernel<<<fggrid, 256>>>(tok);

    cudaMemsetAsync(out, 0, NB*NCLS*sizeof(float));
    logits_kernel<<<NB*NCLS*8, 256>>>(tok, finW, finb, out);

    float* zdst;
    if (out_size >= NB*NCLS + ROWS*ND) zdst = out + NB*NCLS;
    else cudaGetSymbolAddress((void**)&zdst, g_Zdump);
    chord_all_kernel<<<NB*16, 512, chord_smem>>>(tok, zdst);
}

// round 8
// speedup vs baseline: 4.1309x; 1.5791x over previous
#include <cuda_runtime.h>
#include <math.h>

#define NB   32
#define NS   4096
#define ND   64
#define NL   13
#define NWR  13
#define NCLS 2
#define ROWS (NB*NS)          // 131072
#define SD   (NS*ND)          // 262144
#define VOCAB 512

__device__ float g_Vtab[VOCAB*ND];                  // [v][64]
__device__ float g_Ftab[(size_t)NWR*VOCAB*16];      // [k][v][16] (13 used)
__device__ float g_FgT[(size_t)NWR*NB*NL*NS];       // [k*NB+b][l][i]  88.6 MB
__device__ float g_Zdump[(size_t)ROWS*ND];          // fallback Z sink

__device__ __forceinline__ float gelu_exact(float x) {
    return 0.5f * x * (1.0f + erff(x * 0.7071067811865476f));
}

// ---------------------------------------------------------------------------
// Tables: grid (16, 14), block 512. y==0 -> Vtab, y==1..13 -> Ftab[y-1].
// ---------------------------------------------------------------------------
__global__ __launch_bounds__(512) void tables_kernel(
    const float* __restrict__ emb,
    const float* __restrict__ fW1, const float* __restrict__ fb1,
    const float* __restrict__ fW2, const float* __restrict__ fb2,
    const float* __restrict__ vW1, const float* __restrict__ vb1,
    const float* __restrict__ vW2, const float* __restrict__ vb2) {
    extern __shared__ float sm[];
    float* Es  = sm;                    // 2048
    float* W1s = sm + 2048;             // 8192
    float* Hs  = sm + 10240;            // 128*33 = 4224
    float* W2s = sm + 14464;            // up to 8192

    const int y  = blockIdx.y;
    const int v0 = blockIdx.x * 32;
    const int t  = threadIdx.x;

    for (int i = t; i < 2048; i += 512) Es[i] = emb[v0*64 + i];
    const float* W1g = (y == 0) ? vW1 : fW1 + (size_t)(y-1)*64*128;
    for (int i = t; i < 8192; i += 512) W1s[i] = W1g[i];
    if (y == 0) {
        for (int i = t; i < 8192; i += 512) W2s[i] = vW2[i];
    } else {
        const float* W2g = fW2 + (size_t)(y-1)*128*NL;
        for (int i = t; i < 128*NL; i += 512) W2s[i] = W2g[i];
    }
    __syncthreads();

    {
        const int h  = t & 127;
        const int rg = t >> 7;
        float w[64];
#pragma unroll
        for (int d = 0; d < 64; d++) w[d] = W1s[d*128 + h];
        const float b1 = (y == 0) ? vb1[h] : fb1[(y-1)*128 + h];
#pragma unroll 1
        for (int rr = 0; rr < 8; rr++) {
            int r = rg*8 + rr;
            float a0=0.f, a1=0.f, a2=0.f, a3=0.f;
#pragma unroll
            for (int d4 = 0; d4 < 16; d4++) {
                a0 = fmaf(Es[r*64 + 4*d4+0], w[4*d4+0], a0);
                a1 = fmaf(Es[r*64 + 4*d4+1], w[4*d4+1], a1);
                a2 = fmaf(Es[r*64 + 4*d4+2], w[4*d4+2], a2);
                a3 = fmaf(Es[r*64 + 4*d4+3], w[4*d4+3], a3);
            }
            Hs[h*33 + r] = gelu_exact(b1 + ((a0+a1)+(a2+a3)));
        }
    }
    __syncthreads();

    if (y == 0) {
        const int d = t & 63, rgrp = t >> 6;
#pragma unroll 1
        for (int rr = 0; rr < 4; rr++) {
            int r = rgrp*4 + rr;
            float a0=0.f, a1=0.f, a2=0.f, a3=0.f;
#pragma unroll
            for (int h4 = 0; h4 < 32; h4++) {
                a0 = fmaf(Hs[(4*h4+0)*33 + r], W2s[(4*h4+0)*64 + d], a0);
                a1 = fmaf(Hs[(4*h4+1)*33 + r], W2s[(4*h4+1)*64 + d], a1);
                a2 = fmaf(Hs[(4*h4+2)*33 + r], W2s[(4*h4+2)*64 + d], a2);
                a3 = fmaf(Hs[(4*h4+3)*33 + r], W2s[(4*h4+3)*64 + d], a3);
            }
            g_Vtab[(size_t)(v0 + r)*64 + d] = vb2[d] + ((a0+a1)+(a2+a3));
        }
    } else {
        const int k = y - 1;
        if (t < 32*NL) {
            int l = t >> 5, r = t & 31;
            float a0=0.f, a1=0.f, a2=0.f, a3=0.f;
#pragma unroll
            for (int h4 = 0; h4 < 32; h4++) {
                a0 = fmaf(Hs[(4*h4+0)*33 + r], W2s[(4*h4+0)*NL + l], a0);
                a1 = fmaf(Hs[(4*h4+1)*33 + r], W2s[(4*h4+1)*NL + l], a1);
                a2 = fmaf(Hs[(4*h4+2)*33 + r], W2s[(4*h4+2)*NL + l], a2);
                a3 = fmaf(Hs[(4*h4+3)*33 + r], W2s[(4*h4+3)*NL + l], a3);
            }
            g_Ftab[((size_t)k*VOCAB + v0 + r)*16 + l] = fb2[k*NL + l] + ((a0+a1)+(a2+a3));
        }
    }
}

// ---------------------------------------------------------------------------
// F expansion: FgT[(k*NB+b)*13 + l][i] = Ftab[k][tok[b][i]][l]
// Coalesced 4B stores per l-plane.
// ---------------------------------------------------------------------------
__global__ __launch_bounds__(256) void fgather_kernel(const int* __restrict__ tok) {
    const int i  = blockIdx.x * 256 + threadIdx.x;
    const int kb = blockIdx.y;          // k*NB + b
    const int k  = kb >> 5;
    const int b  = kb & 31;
    const int v  = tok[(size_t)b*NS + i];

    const float4* src = (const float4*)g_Ftab + ((size_t)k*VOCAB + v)*4;
    float4 q0 = src[0], q1 = src[1], q2 = src[2], q3 = src[3];
    const float f[13] = {q0.x,q0.y,q0.z,q0.w, q1.x,q1.y,q1.z,q1.w,
                         q2.x,q2.y,q2.z,q2.w, q3.x};
    float* dst = g_FgT + ((size_t)kb*NL)*NS + i;
#pragma unroll
    for (int l = 0; l < NL; l++) dst[(size_t)l*NS] = f[l];
}

// ---------------------------------------------------------------------------
// Logits
// ---------------------------------------------------------------------------
__global__ __launch_bounds__(256) void logits_kernel(
    const int* __restrict__ tok,
    const float* __restrict__ finW, const float* __restrict__ finb,
    float* __restrict__ out) {
    const int s = blockIdx.x & 7;
    const int c = (blockIdx.x >> 3) & 1;
    const int b = blockIdx.x >> 4;
    const int t = threadIdx.x;
    const int chunk = SD/4/8;   // 8192 float4

    const float4* Vt4 = (const float4*)g_Vtab;
    const float4* w   = (const float4*)(finW + (size_t)c*SD) + s*chunk;
    const int*    tkb = tok + (size_t)b*NS;

    float acc = 0.f;
    for (int i = t; i < chunk; i += 256) {
        int gi   = s*chunk + i;
        int srow = gi >> 4;
        int d4   = gi & 15;
        float4 vv = Vt4[tkb[srow]*16 + d4];
        float4 ww = w[i];
        acc = fmaf(vv.x, ww.x, acc);
        acc = fmaf(vv.y, ww.y, acc);
        acc = fmaf(vv.z, ww.z, acc);
        acc = fmaf(vv.w, ww.w, acc);
    }
    __shared__ float red[256];
    red[t] = acc;
    __syncthreads();
#pragma unroll
    for (int sft = 128; sft > 0; sft >>= 1) {
        if (t < sft) red[t] += red[t + sft];
        __syncthreads();
    }
    if (t == 0) atomicAdd(&out[b*NCLS + c], red[0] + (s == 0 ? finb[c] : 0.f));
}

// ---------------------------------------------------------------------------
// Fused chord, all 13 rounds. Block = (b, cp 0..15) -> 4 cols c0=cp*4.
// 1024 threads; thread t owns i = t + 1024m (m=0..3).
// Links 0/1024/2048 from registers (zreg); links 1..512 from float4 smem
// plane Zs; V residual from float4 smem plane Vp (staged once).
// 64-reg budget -> no spills; 32 warps/SM.
// ---------------------------------------------------------------------------
__global__ __launch_bounds__(1024, 1) void chord_all_kernel(
    const int* __restrict__ tok, float* __restrict__ outZ) {
    extern __shared__ float sm[];
    float4* Zs = (float4*)sm;            // [i], 64 KB
    float4* Vp = Zs + NS;                // [i], 64 KB

    const int b  = blockIdx.x >> 4;
    const int cp = blockIdx.x & 15;
    const int c0 = cp * 4;
    const int t  = threadIdx.x;

    // init: gather V for own rows, write Vp and Zs
    float4 zreg[4];
    {
        const int* tkb = tok + (size_t)b*NS;
#pragma unroll
        for (int m = 0; m < 4; m++) {
            const int i = t + 1024*m;
            const int v = tkb[i];
            float4 a = *(const float4*)(g_Vtab + (size_t)v*64 + c0);
            Vp[i] = a;
            Zs[i] = a;
            zreg[m] = a;
        }
    }
    __syncthreads();

    float4 acc[4];
#pragma unroll 1
    for (int k = 0; k < NWR; k++) {
        const float* Fb = g_FgT + ((size_t)(k*NB + b)*NL)*NS + t;
#pragma unroll
        for (int m = 0; m < 4; m++) {
            const int i = t + 1024*m;
            const float* fp = Fb + 1024*m;
            const float f0  = fp[0];
            const float f1  = fp[(size_t)1*NS],  f2  = fp[(size_t)2*NS];
            const float f3  = fp[(size_t)3*NS],  f4  = fp[(size_t)4*NS];
            const float f5  = fp[(size_t)5*NS],  f6  = fp[(size_t)6*NS];
            const float f7  = fp[(size_t)7*NS],  f8  = fp[(size_t)8*NS];
            const float f9  = fp[(size_t)9*NS],  f10 = fp[(size_t)10*NS];
            const float f11 = fp[(size_t)11*NS], f12 = fp[(size_t)12*NS];

            // V residual (conflict-free float4)
            float4 a = Vp[i];

            // register links: off 0 (f0), 1024 (f11), 2048 (f12)
            const int m1 = (m+1)&3, m2 = (m+2)&3;
            a.x = fmaf(f0,  zreg[m ].x, a.x); a.y = fmaf(f0,  zreg[m ].y, a.y);
            a.z = fmaf(f0,  zreg[m ].z, a.z); a.w = fmaf(f0,  zreg[m ].w, a.w);
            a.x = fmaf(f11, zreg[m1].x, a.x); a.y = fmaf(f11, zreg[m1].y, a.y);
            a.z = fmaf(f11, zreg[m1].z, a.z); a.w = fmaf(f11, zreg[m1].w, a.w);
            a.x = fmaf(f12, zreg[m2].x, a.x); a.y = fmaf(f12, zreg[m2].y, a.y);
            a.z = fmaf(f12, zreg[m2].z, a.z); a.w = fmaf(f12, zreg[m2].w, a.w);

            // smem links: off 1..512 (f1..f10)
            const float fs[10] = {f1,f2,f3,f4,f5,f6,f7,f8,f9,f10};
            const int offs[10] = {1,2,4,8,16,32,64,128,256,512};
#pragma unroll
            for (int li = 0; li < 10; li++) {
                const int j = (i + offs[li]) & (NS-1);
                const float fl = fs[li];
                float4 z = Zs[j];
                a.x = fmaf(fl, z.x, a.x); a.y = fmaf(fl, z.y, a.y);
                a.z = fmaf(fl, z.z, a.z); a.w = fmaf(fl, z.w, a.w);
            }
            acc[m] = a;
        }
        __syncthreads();
#pragma unroll
        for (int m = 0; m < 4; m++) {
            zreg[m] = acc[m];
            Zs[t + 1024*m] = acc[m];
        }
        __syncthreads();
    }

    // final Z -> gmem
#pragma unroll
    for (int m = 0; m < 4; m++) {
        const int i = t + 1024*m;
        *(float4*)(outZ + ((size_t)b*NS + i)*64 + c0) = acc[m];
    }
}

// ---------------------------------------------------------------------------
extern "C" void kernel_launch(void* const* d_in, const int* in_sizes, int n_in,
                              void* d_out, int out_size) {
    const int*   tok  = (const int*)  d_in[0];
    const float* emb  = (const float*)d_in[1];
    const float* fW1  = (const float*)d_in[2];
    const float* fb1  = (const float*)d_in[3];
    const float* fW2  = (const float*)d_in[4];
    const float* fb2  = (const float*)d_in[5];
    const float* vW1  = (const float*)d_in[6];
    const float* vb1  = (const float*)d_in[7];
    const float* vW2  = (const float*)d_in[8];
    const float* vb2  = (const float*)d_in[9];
    const float* finW = (const float*)d_in[10];
    const float* finb = (const float*)d_in[11];
    float* out = (float*)d_out;

    const int tables_smem = (2048 + 8192 + 4224 + 8192) * 4;   // 90624
    const int chord_smem  = NS * 2 * 16;                       // 131072
    cudaFuncSetAttribute(tables_kernel,    cudaFuncAttributeMaxDynamicSharedMemorySize, tables_smem);
    cudaFuncSetAttribute(chord_all_kernel, cudaFuncAttributeMaxDynamicSharedMemorySize, chord_smem);

    dim3 tgrid(16, 14);
    tables_kernel<<<tgrid, 512, tables_smem>>>(emb, fW1, fb1, fW2, fb2,
                                               vW1, vb1, vW2, vb2);

    dim3 fggrid(NS/256, NWR*NB);
    fgather_kernel<<<fggrid, 256>>>(tok);

    cudaMemsetAsync(out, 0, NB*NCLS*sizeof(float));
    logits_kernel<<<NB*NCLS*8, 256>>>(tok, finW, finb, out);

    float* zdst;
    if (out_size >= NB*NCLS + ROWS*ND) zdst = out + NB*NCLS;
    else cudaGetSymbolAddress((void**)&zdst, g_Zdump);
    chord_all_kernel<<<NB*16, 1024, chord_smem>>>(tok, zdst);
}